// round 1
// baseline (speedup 1.0000x reference)
#include <cuda_runtime.h>
#include <cuda_bf16.h>
#include <math.h>

// Problem constants
#define LNUM 4
#define DD   256
#define HH   8
#define INNER 2048          // H * DH, DH == D == 256
#define MM   1024           // mlp dim
#define BB   8
#define NN_  1024
#define ROWS (BB*NN_)       // 8192
#define QKV_N (3*INNER)     // 6144
#define SCALE_ 0.0625f      // 256^-0.5

// ---------------- device scratch (static globals; no allocation allowed) ----
__device__ float g_h[(size_t)ROWS*DD];               // 8 MB   LN output
__device__ float g_qkv[(size_t)ROWS*QKV_N];          // 201 MB qkv activations
__device__ float g_scores[(size_t)64*1024*1024];     // 256 MB attention scores
__device__ float g_attn[(size_t)ROWS*INNER];         // 67 MB  attention output
__device__ float g_mlp[(size_t)ROWS*MM];             // 33 MB  mlp hidden

// ---------------- LayerNorm: one block (256 thr) per row of 256 ------------
__global__ void ln_kernel(const float* __restrict__ x,
                          const float* __restrict__ g,
                          const float* __restrict__ b,
                          float* __restrict__ out) {
    const int row = blockIdx.x;
    const int t   = threadIdx.x;
    float v = x[(size_t)row*DD + t];

    float s1 = v, s2 = v*v;
    #pragma unroll
    for (int o = 16; o > 0; o >>= 1) {
        s1 += __shfl_down_sync(0xffffffffu, s1, o);
        s2 += __shfl_down_sync(0xffffffffu, s2, o);
    }
    __shared__ float w1[8], w2[8];
    const int lane = t & 31, wid = t >> 5;
    if (lane == 0) { w1[wid] = s1; w2[wid] = s2; }
    __syncthreads();
    __shared__ float smu, srs;
    if (t == 0) {
        float a = 0.f, c = 0.f;
        #pragma unroll
        for (int i = 0; i < 8; i++) { a += w1[i]; c += w2[i]; }
        float mu  = a / DD;
        float var = c / DD - mu*mu;
        smu = mu;
        srs = rsqrtf(var + 1e-5f);
    }
    __syncthreads();
    out[(size_t)row*DD + t] = (v - smu) * srs * g[t] + b[t];
}

// ---------------- row softmax over 1024 cols --------------------------------
__global__ void softmax_kernel(float* __restrict__ s) {
    float* p = s + (size_t)blockIdx.x * 1024;
    const int t = threadIdx.x;
    float v0 = p[t], v1 = p[t+256], v2 = p[t+512], v3 = p[t+768];

    float m = fmaxf(fmaxf(v0, v1), fmaxf(v2, v3));
    #pragma unroll
    for (int o = 16; o > 0; o >>= 1) m = fmaxf(m, __shfl_down_sync(0xffffffffu, m, o));
    __shared__ float wm[8];
    const int lane = t & 31, wid = t >> 5;
    if (lane == 0) wm[wid] = m;
    __syncthreads();
    __shared__ float bm;
    if (t == 0) {
        float a = wm[0];
        #pragma unroll
        for (int i = 1; i < 8; i++) a = fmaxf(a, wm[i]);
        bm = a;
    }
    __syncthreads();
    m = bm;
    v0 = expf(v0 - m); v1 = expf(v1 - m); v2 = expf(v2 - m); v3 = expf(v3 - m);

    float s1 = v0 + v1 + v2 + v3;
    #pragma unroll
    for (int o = 16; o > 0; o >>= 1) s1 += __shfl_down_sync(0xffffffffu, s1, o);
    __shared__ float ws[8];
    if (lane == 0) ws[wid] = s1;
    __syncthreads();
    __shared__ float bs_;
    if (t == 0) {
        float a = 0.f;
        #pragma unroll
        for (int i = 0; i < 8; i++) a += ws[i];
        bs_ = a;
    }
    __syncthreads();
    const float inv = 1.f / bs_;
    p[t] = v0*inv; p[t+256] = v1*inv; p[t+512] = v2*inv; p[t+768] = v3*inv;
}

// ---------------- generic tiled fp32 GEMM ----------------------------------
// C = alpha * A @ op(B) (+ bias) (+gelu | +residual)
// TB=false: B is [K,N] row-major. TB=true: B is [N,K] row-major (use B^T).
// Batched over blockIdx.z with (b = z/8, h = z%8) offsets.
// All dims: M%64==0, N%64==0, K%16==0 (guaranteed by problem shapes).
// EPI: 0 none, 1 +bias, 2 +bias+gelu, 3 +bias+residual
template<int EPI, bool TB>
__global__ void __launch_bounds__(256)
gemm_kernel(const float* __restrict__ A, const float* __restrict__ B,
            const float* __restrict__ bias, const float* __restrict__ res,
            float* __restrict__ C,
            int M, int N, int K, int lda, int ldb, int ldc,
            long long sAb, long long sAh, long long sBb, long long sBh,
            long long sCb, long long sCh, float alpha)
{
    const int bb = blockIdx.z >> 3;
    const int hh = blockIdx.z & 7;
    A += (size_t)bb*sAb + (size_t)hh*sAh;
    B += (size_t)bb*sBb + (size_t)hh*sBh;
    C += (size_t)bb*sCb + (size_t)hh*sCh;

    const int row0 = blockIdx.y * 64;
    const int col0 = blockIdx.x * 64;
    const int tid  = threadIdx.x;
    const int tx   = tid & 15;      // column group
    const int ty   = tid >> 4;      // row group

    __shared__ float As[16][65];
    __shared__ float Bs[16][65];

    float acc[4][4] = {};

    for (int kk = 0; kk < K; kk += 16) {
        // load A tile (64 x 16) -> As[k][m]
        #pragma unroll
        for (int i = 0; i < 4; i++) {
            int idx = tid + i*256;
            int r = idx >> 4, c = idx & 15;
            As[c][r] = A[(size_t)(row0 + r)*lda + kk + c];
        }
        // load B tile -> Bs[k][n]
        if (TB) {
            #pragma unroll
            for (int i = 0; i < 4; i++) {
                int idx = tid + i*256;
                int c = idx & 15, r = idx >> 4;      // c=k, r=n
                Bs[c][r] = B[(size_t)(col0 + r)*ldb + kk + c];
            }
        } else {
            #pragma unroll
            for (int i = 0; i < 4; i++) {
                int idx = tid + i*256;
                int r = idx >> 6, c = idx & 63;      // r=k, c=n
                Bs[r][c] = B[(size_t)(kk + r)*ldb + col0 + c];
            }
        }
        __syncthreads();

        #pragma unroll
        for (int k = 0; k < 16; k++) {
            float a[4], bv[4];
            #pragma unroll
            for (int i = 0; i < 4; i++) a[i]  = As[k][ty*4 + i];
            #pragma unroll
            for (int j = 0; j < 4; j++) bv[j] = Bs[k][tx*4 + j];
            #pragma unroll
            for (int i = 0; i < 4; i++)
                #pragma unroll
                for (int j = 0; j < 4; j++)
                    acc[i][j] += a[i] * bv[j];
        }
        __syncthreads();
    }

    #pragma unroll
    for (int i = 0; i < 4; i++) {
        const int r = row0 + ty*4 + i;
        #pragma unroll
        for (int j = 0; j < 4; j++) {
            const int cg = col0 + tx*4 + j;
            float v = acc[i][j] * alpha;
            if (EPI >= 1) v += bias[cg];
            if (EPI == 2) v = 0.5f * v * (1.0f + erff(v * 0.70710678118654752f));
            if (EPI == 3) v += res[(size_t)r*ldc + cg];
            C[(size_t)r*ldc + cg] = v;
        }
    }
}

// ---------------- host launcher --------------------------------------------
extern "C" void kernel_launch(void* const* d_in, const int* in_sizes, int n_in,
                              void* d_out, int out_size) {
    const float* inputs = (const float*)d_in[0];
    const float* ln1_g  = (const float*)d_in[1];
    const float* ln1_b  = (const float*)d_in[2];
    const float* w_qkv  = (const float*)d_in[3];
    const float* w_proj = (const float*)d_in[4];
    const float* b_proj = (const float*)d_in[5];
    const float* ln2_g  = (const float*)d_in[6];
    const float* ln2_b  = (const float*)d_in[7];
    const float* w1     = (const float*)d_in[8];
    const float* b1     = (const float*)d_in[9];
    const float* w2     = (const float*)d_in[10];
    const float* b2     = (const float*)d_in[11];
    float* x = (float*)d_out;   // residual stream lives in d_out

    float *ph, *pqkv, *pscores, *pattn, *pmlp;
    cudaGetSymbolAddress((void**)&ph,      g_h);
    cudaGetSymbolAddress((void**)&pqkv,    g_qkv);
    cudaGetSymbolAddress((void**)&pscores, g_scores);
    cudaGetSymbolAddress((void**)&pattn,   g_attn);
    cudaGetSymbolAddress((void**)&pmlp,    g_mlp);

    // x = inputs
    cudaMemcpyAsync(x, inputs, (size_t)ROWS*DD*sizeof(float),
                    cudaMemcpyDeviceToDevice);

    const dim3 blk(256);

    for (int l = 0; l < LNUM; l++) {
        // ---- pre-LN 1 ----
        ln_kernel<<<ROWS, blk>>>(x, ln1_g + l*DD, ln1_b + l*DD, ph);

        // ---- qkv = h @ w_qkv[l]   [8192,256]x[256,6144] ----
        gemm_kernel<0,false><<<dim3(QKV_N/64, ROWS/64, 1), blk>>>(
            ph, w_qkv + (size_t)l*DD*QKV_N, nullptr, nullptr, pqkv,
            ROWS, QKV_N, DD, DD, QKV_N, QKV_N,
            0,0,0,0,0,0, 1.0f);

        // ---- scores = SCALE * Q @ K^T   per (b,h): [1024,256]x[256,1024] ----
        gemm_kernel<0,true><<<dim3(1024/64, 1024/64, 64), blk>>>(
            pqkv, pqkv + INNER, nullptr, nullptr, pscores,
            1024, 1024, DD, QKV_N, QKV_N, 1024,
            /*sAb*/ (long long)NN_*QKV_N, /*sAh*/ DD,
            /*sBb*/ (long long)NN_*QKV_N, /*sBh*/ DD,
            /*sCb*/ 8LL*1024*1024,        /*sCh*/ 1024LL*1024,
            SCALE_);

        // ---- softmax over last dim ----
        softmax_kernel<<<64*1024, blk>>>(pscores);

        // ---- attn_out = P @ V   per (b,h): [1024,1024]x[1024,256] ----
        gemm_kernel<0,false><<<dim3(DD/64, 1024/64, 64), blk>>>(
            pscores, pqkv + 2*INNER, nullptr, nullptr, pattn,
            1024, DD, 1024, 1024, QKV_N, INNER,
            /*sAb*/ 8LL*1024*1024,        /*sAh*/ 1024LL*1024,
            /*sBb*/ (long long)NN_*QKV_N, /*sBh*/ DD,
            /*sCb*/ (long long)NN_*INNER, /*sCh*/ DD,
            1.0f);

        // ---- x = x + attn_out @ w_proj[l] + b_proj[l] ----
        gemm_kernel<3,false><<<dim3(DD/64, ROWS/64, 1), blk>>>(
            pattn, w_proj + (size_t)l*INNER*DD, b_proj + l*DD, x, x,
            ROWS, DD, INNER, INNER, DD, DD,
            0,0,0,0,0,0, 1.0f);

        // ---- pre-LN 2 ----
        ln_kernel<<<ROWS, blk>>>(x, ln2_g + l*DD, ln2_b + l*DD, ph);

        // ---- hidden = gelu(h @ w1[l] + b1[l]) ----
        gemm_kernel<2,false><<<dim3(MM/64, ROWS/64, 1), blk>>>(
            ph, w1 + (size_t)l*DD*MM, b1 + l*MM, nullptr, pmlp,
            ROWS, MM, DD, DD, MM, MM,
            0,0,0,0,0,0, 1.0f);

        // ---- x = x + hidden @ w2[l] + b2[l] ----
        gemm_kernel<3,false><<<dim3(DD/64, ROWS/64, 1), blk>>>(
            pmlp, w2 + (size_t)l*MM*DD, b2 + l*DD, x, x,
            ROWS, DD, MM, MM, DD, DD,
            0,0,0,0,0,0, 1.0f);
    }
}

// round 2
// speedup vs baseline: 3.5033x; 3.5033x over previous
#include <cuda_runtime.h>
#include <cuda_bf16.h>
#include <math.h>

// Problem constants
#define LNUM 4
#define DD   256
#define HH   8
#define INNER 2048
#define MM   1024
#define BB   8
#define NN_  1024
#define ROWS (BB*NN_)       // 8192
#define QKV_N (3*INNER)     // 6144
#define SCALE_ 0.0625f

// ---------------- device scratch ----------------
__device__ float g_h[(size_t)ROWS*DD];
__device__ float g_qkv[(size_t)ROWS*QKV_N];
__device__ float g_scores[(size_t)64*1024*1024];
__device__ float g_attn[(size_t)ROWS*INNER];
__device__ float g_mlp[(size_t)ROWS*MM];
__device__ float g_kT[(size_t)64*DD*NN_];      // per (b,h): K^T [256][1024]

__device__ __forceinline__ unsigned f2tf32(float x) {
    unsigned r;
    asm("cvt.rna.tf32.f32 %0, %1;" : "=r"(r) : "f"(x));
    return r;
}

// ---------------- LayerNorm ----------------
__global__ void ln_kernel(const float* __restrict__ x,
                          const float* __restrict__ g,
                          const float* __restrict__ b,
                          float* __restrict__ out) {
    const int row = blockIdx.x;
    const int t   = threadIdx.x;
    float v = x[(size_t)row*DD + t];
    float s1 = v, s2 = v*v;
    #pragma unroll
    for (int o = 16; o > 0; o >>= 1) {
        s1 += __shfl_down_sync(0xffffffffu, s1, o);
        s2 += __shfl_down_sync(0xffffffffu, s2, o);
    }
    __shared__ float w1[8], w2[8];
    const int lane = t & 31, wid = t >> 5;
    if (lane == 0) { w1[wid] = s1; w2[wid] = s2; }
    __syncthreads();
    __shared__ float smu, srs;
    if (t == 0) {
        float a = 0.f, c = 0.f;
        #pragma unroll
        for (int i = 0; i < 8; i++) { a += w1[i]; c += w2[i]; }
        float mu  = a / DD;
        float var = c / DD - mu*mu;
        smu = mu;
        srs = rsqrtf(var + 1e-5f);
    }
    __syncthreads();
    out[(size_t)row*DD + t] = (v - smu) * srs * g[t] + b[t];
}

// ---------------- softmax over 1024 cols ----------------
__global__ void softmax_kernel(float* __restrict__ s) {
    float* p = s + (size_t)blockIdx.x * 1024;
    const int t = threadIdx.x;
    float v0 = p[t], v1 = p[t+256], v2 = p[t+512], v3 = p[t+768];
    float m = fmaxf(fmaxf(v0, v1), fmaxf(v2, v3));
    #pragma unroll
    for (int o = 16; o > 0; o >>= 1) m = fmaxf(m, __shfl_down_sync(0xffffffffu, m, o));
    __shared__ float wm[8];
    const int lane = t & 31, wid = t >> 5;
    if (lane == 0) wm[wid] = m;
    __syncthreads();
    __shared__ float bm;
    if (t == 0) {
        float a = wm[0];
        #pragma unroll
        for (int i = 1; i < 8; i++) a = fmaxf(a, wm[i]);
        bm = a;
    }
    __syncthreads();
    m = bm;
    v0 = expf(v0 - m); v1 = expf(v1 - m); v2 = expf(v2 - m); v3 = expf(v3 - m);
    float s1 = v0 + v1 + v2 + v3;
    #pragma unroll
    for (int o = 16; o > 0; o >>= 1) s1 += __shfl_down_sync(0xffffffffu, s1, o);
    __shared__ float ws[8];
    if (lane == 0) ws[wid] = s1;
    __syncthreads();
    __shared__ float bs_;
    if (t == 0) {
        float a = 0.f;
        #pragma unroll
        for (int i = 0; i < 8; i++) a += ws[i];
        bs_ = a;
    }
    __syncthreads();
    const float inv = 1.f / bs_;
    p[t] = v0*inv; p[t+256] = v1*inv; p[t+512] = v2*inv; p[t+768] = v3*inv;
}

// ---------------- K transpose: qkv K-part -> kT[bh][d][n] ----------------
__global__ void transpose_k(const float* __restrict__ qkv, float* __restrict__ kT) {
    __shared__ float tile[32][33];
    const int bh = blockIdx.z, bb = bh >> 3, hh = bh & 7;
    const float* src = qkv + (size_t)bb*NN_*QKV_N + INNER + hh*DD;
    const int n0 = blockIdx.x*32, d0 = blockIdx.y*32;
    #pragma unroll
    for (int i = threadIdx.y; i < 32; i += 8)
        tile[i][threadIdx.x] = src[(size_t)(n0+i)*QKV_N + d0 + threadIdx.x];
    __syncthreads();
    float* dst = kT + (size_t)bh*DD*NN_;
    #pragma unroll
    for (int i = threadIdx.y; i < 32; i += 8)
        dst[(size_t)(d0+i)*NN_ + n0 + threadIdx.x] = tile[threadIdx.x][i];
}

// ---------------- tf32 tensor-core GEMM ----------------
// C = alpha * A[M,K] @ B[K,N] (+bias)(+gelu|+residual); all row-major.
// Block tile 128x64, 8 warps of 32x32, K-chunk 32.
// EPI: 0 none, 1 +bias, 2 +bias+gelu, 3 +bias+residual
template<int EPI>
__global__ void __launch_bounds__(256)
gemm_tf32(const float* __restrict__ A, const float* __restrict__ B,
          const float* __restrict__ bias, const float* __restrict__ res,
          float* __restrict__ C,
          int M, int N, int K, int lda, int ldb, int ldc,
          long long sAb, long long sAh, long long sBb, long long sBh,
          long long sCb, long long sCh, float alpha)
{
    const int bb = blockIdx.z >> 3;
    const int hh = blockIdx.z & 7;
    A += (size_t)bb*sAb + (size_t)hh*sAh;
    B += (size_t)bb*sBb + (size_t)hh*sBh;
    C += (size_t)bb*sCb + (size_t)hh*sCh;

    const int row0 = blockIdx.y * 128;
    const int col0 = blockIdx.x * 64;
    const int tid  = threadIdx.x;
    const int lane = tid & 31, wid = tid >> 5;
    const int wr = wid & 3, wc = wid >> 2;     // warp tile: rows wr*32, cols wc*32
    const int g  = lane >> 2, t4 = lane & 3;

    __shared__ unsigned As[128][36];   // pad 36: frag banks 4g+t4, conflict-free
    __shared__ unsigned Bs[32][72];    // pad 72: frag banks 8t4+g, conflict-free

    float acc[2][4][4] = {};

    for (int kk = 0; kk < K; kk += 32) {
        // A tile 128x32
        #pragma unroll
        for (int i = 0; i < 4; i++) {
            int f4 = tid + i*256;
            int r = f4 >> 3, c4 = (f4 & 7) * 4;
            float4 v = *reinterpret_cast<const float4*>(
                &A[(size_t)(row0 + r)*lda + kk + c4]);
            As[r][c4+0] = f2tf32(v.x);
            As[r][c4+1] = f2tf32(v.y);
            As[r][c4+2] = f2tf32(v.z);
            As[r][c4+3] = f2tf32(v.w);
        }
        // B tile 32x64
        #pragma unroll
        for (int i = 0; i < 2; i++) {
            int f4 = tid + i*256;
            int r = f4 >> 4, c4 = (f4 & 15) * 4;
            float4 v = *reinterpret_cast<const float4*>(
                &B[(size_t)(kk + r)*ldb + col0 + c4]);
            Bs[r][c4+0] = f2tf32(v.x);
            Bs[r][c4+1] = f2tf32(v.y);
            Bs[r][c4+2] = f2tf32(v.z);
            Bs[r][c4+3] = f2tf32(v.w);
        }
        __syncthreads();

        #pragma unroll
        for (int k8 = 0; k8 < 4; k8++) {
            const int kb = k8*8;
            unsigned a[2][4], b[4][2];
            #pragma unroll
            for (int m = 0; m < 2; m++) {
                const int r = wr*32 + m*16;
                a[m][0] = As[r+g  ][kb+t4  ];
                a[m][1] = As[r+g+8][kb+t4  ];
                a[m][2] = As[r+g  ][kb+t4+4];
                a[m][3] = As[r+g+8][kb+t4+4];
            }
            #pragma unroll
            for (int n = 0; n < 4; n++) {
                const int c = wc*32 + n*8 + g;
                b[n][0] = Bs[kb+t4  ][c];
                b[n][1] = Bs[kb+t4+4][c];
            }
            #pragma unroll
            for (int m = 0; m < 2; m++)
                #pragma unroll
                for (int n = 0; n < 4; n++)
                    asm volatile(
                        "mma.sync.aligned.m16n8k8.row.col.f32.tf32.tf32.f32 "
                        "{%0,%1,%2,%3}, {%4,%5,%6,%7}, {%8,%9}, {%0,%1,%2,%3};"
                        : "+f"(acc[m][n][0]), "+f"(acc[m][n][1]),
                          "+f"(acc[m][n][2]), "+f"(acc[m][n][3])
                        : "r"(a[m][0]), "r"(a[m][1]), "r"(a[m][2]), "r"(a[m][3]),
                          "r"(b[n][0]), "r"(b[n][1]));
        }
        __syncthreads();
    }

    // epilogue
    #pragma unroll
    for (int m = 0; m < 2; m++) {
        const int rbase = row0 + wr*32 + m*16 + g;
        #pragma unroll
        for (int n = 0; n < 4; n++) {
            const int c = col0 + wc*32 + n*8 + 2*t4;
            #pragma unroll
            for (int h = 0; h < 2; h++) {
                const int r = rbase + h*8;
                float v0 = acc[m][n][2*h+0] * alpha;
                float v1 = acc[m][n][2*h+1] * alpha;
                if (EPI >= 1) { v0 += bias[c]; v1 += bias[c+1]; }
                if (EPI == 2) {
                    v0 = 0.5f * v0 * (1.0f + erff(v0 * 0.70710678118654752f));
                    v1 = 0.5f * v1 * (1.0f + erff(v1 * 0.70710678118654752f));
                }
                if (EPI == 3) {
                    v0 += res[(size_t)r*ldc + c];
                    v1 += res[(size_t)r*ldc + c + 1];
                }
                *reinterpret_cast<float2*>(&C[(size_t)r*ldc + c]) =
                    make_float2(v0, v1);
            }
        }
    }
}

// ---------------- host launcher ----------------
extern "C" void kernel_launch(void* const* d_in, const int* in_sizes, int n_in,
                              void* d_out, int out_size) {
    const float* inputs = (const float*)d_in[0];
    const float* ln1_g  = (const float*)d_in[1];
    const float* ln1_b  = (const float*)d_in[2];
    const float* w_qkv  = (const float*)d_in[3];
    const float* w_proj = (const float*)d_in[4];
    const float* b_proj = (const float*)d_in[5];
    const float* ln2_g  = (const float*)d_in[6];
    const float* ln2_b  = (const float*)d_in[7];
    const float* w1     = (const float*)d_in[8];
    const float* b1     = (const float*)d_in[9];
    const float* w2     = (const float*)d_in[10];
    const float* b2     = (const float*)d_in[11];
    float* x = (float*)d_out;

    float *ph, *pqkv, *pscores, *pattn, *pmlp, *pkT;
    cudaGetSymbolAddress((void**)&ph,      g_h);
    cudaGetSymbolAddress((void**)&pqkv,    g_qkv);
    cudaGetSymbolAddress((void**)&pscores, g_scores);
    cudaGetSymbolAddress((void**)&pattn,   g_attn);
    cudaGetSymbolAddress((void**)&pmlp,    g_mlp);
    cudaGetSymbolAddress((void**)&pkT,     g_kT);

    cudaMemcpyAsync(x, inputs, (size_t)ROWS*DD*sizeof(float),
                    cudaMemcpyDeviceToDevice);

    const dim3 blk(256);

    for (int l = 0; l < LNUM; l++) {
        // pre-LN 1
        ln_kernel<<<ROWS, blk>>>(x, ln1_g + l*DD, ln1_b + l*DD, ph);

        // qkv = h @ w_qkv[l]   [8192,256]x[256,6144]
        gemm_tf32<0><<<dim3(QKV_N/64, ROWS/128, 1), blk>>>(
            ph, w_qkv + (size_t)l*DD*QKV_N, nullptr, nullptr, pqkv,
            ROWS, QKV_N, DD, DD, QKV_N, QKV_N,
            0,0,0,0,0,0, 1.0f);

        // transpose K -> kT[bh][d][n]
        transpose_k<<<dim3(32, 8, 64), dim3(32, 8)>>>(pqkv, pkT);

        // scores = SCALE * Q @ kT   per (b,h): [1024,256]x[256,1024]
        gemm_tf32<0><<<dim3(1024/64, 1024/128, 64), blk>>>(
            pqkv, pkT, nullptr, nullptr, pscores,
            1024, 1024, DD, QKV_N, NN_, 1024,
            /*sAb*/ (long long)NN_*QKV_N, /*sAh*/ DD,
            /*sBb*/ 8LL*DD*NN_,           /*sBh*/ (long long)DD*NN_,
            /*sCb*/ 8LL*1024*1024,        /*sCh*/ 1024LL*1024,
            SCALE_);

        // softmax
        softmax_kernel<<<64*1024, blk>>>(pscores);

        // attn_out = P @ V   per (b,h): [1024,1024]x[1024,256]
        gemm_tf32<0><<<dim3(DD/64, 1024/128, 64), blk>>>(
            pscores, pqkv + 2*INNER, nullptr, nullptr, pattn,
            1024, DD, 1024, 1024, QKV_N, INNER,
            /*sAb*/ 8LL*1024*1024,        /*sAh*/ 1024LL*1024,
            /*sBb*/ (long long)NN_*QKV_N, /*sBh*/ DD,
            /*sCb*/ (long long)NN_*INNER, /*sCh*/ DD,
            1.0f);

        // x = x + attn_out @ w_proj[l] + b_proj[l]
        gemm_tf32<3><<<dim3(DD/64, ROWS/128, 1), blk>>>(
            pattn, w_proj + (size_t)l*INNER*DD, b_proj + l*DD, x, x,
            ROWS, DD, INNER, INNER, DD, DD,
            0,0,0,0,0,0, 1.0f);

        // pre-LN 2
        ln_kernel<<<ROWS, blk>>>(x, ln2_g + l*DD, ln2_b + l*DD, ph);

        // hidden = gelu(h @ w1[l] + b1[l])
        gemm_tf32<2><<<dim3(MM/64, ROWS/128, 1), blk>>>(
            ph, w1 + (size_t)l*DD*MM, b1 + l*MM, nullptr, pmlp,
            ROWS, MM, DD, DD, MM, MM,
            0,0,0,0,0,0, 1.0f);

        // x = x + hidden @ w2[l] + b2[l]
        gemm_tf32<3><<<dim3(DD/64, ROWS/128, 1), blk>>>(
            pmlp, w2 + (size_t)l*MM*DD, b2 + l*DD, x, x,
            ROWS, DD, MM, MM, DD, DD,
            0,0,0,0,0,0, 1.0f);
    }
}